// round 14
// baseline (speedup 1.0000x reference)
#include <cuda_runtime.h>
#include <cuda_fp16.h>
#include <cstdint>

// ---------------------------------------------------------------------------
// InflateHexToVertex, factored:
//   Z[j,t,b,v] = hex[b,t,:] @ W[j*D:(j+1)*D, :]   (mma.sync fp16 GEMM, f32 acc)
//   out[b,n,v] = bias[v] + sum_j (idx[n,j] >= 0) * Z[j, idx[n,j], b, v]
//
// Z fp16 (12.6 MB), L2-resident. GEMM: R11 config (stage A + all 3 W_j once,
// 128 KB smem). Gather: R6 inner shape, 4 vertices/block. PDL: gather grid
// launches while GEMM drains (griddepcontrol), preamble overlapped.
// ---------------------------------------------------------------------------

__device__ __half g_Zh[3 * 512 * 32 * 128];

#define OFF_A 0
#define OFF_B 32768                     // B_j at OFF_B + j*32768
#define GEMM_SMEM 131072

__device__ __forceinline__ uint32_t smem_u32(const void* p) {
    uint32_t a;
    asm("{ .reg .u64 t; cvta.to.shared.u64 t, %1; cvt.u32.u64 %0, t; }"
        : "=r"(a) : "l"(p));
    return a;
}

// --- Z = hex(16384x128) @ W(384x128) via mma.sync (R11 config) ----------------
__global__ void __launch_bounds__(256, 1)
gemm_z(const float* __restrict__ A, const float* __restrict__ W,
       int T, int B) {
    extern __shared__ char sm[];
    const uint32_t smb = smem_u32(sm);
    const int tid = threadIdx.x;
    const int wid = tid >> 5;
    const int lane = tid & 31;
    const int m0 = blockIdx.x * 128;

    // ---- stage A tile: fp32 -> fp16, swizzled --------------------------------
    #pragma unroll
    for (int it = 0; it < 8; ++it) {
        int p   = it * 256 + tid;          // 2048 chunks
        int row = p >> 4;
        int c   = p & 15;
        const float* src = A + (size_t)(m0 + row) * 128 + c * 8;
        float4 f0 = *(const float4*)src;
        float4 f1 = *(const float4*)(src + 4);
        __half2 h[4] = {__floats2half2_rn(f0.x, f0.y), __floats2half2_rn(f0.z, f0.w),
                        __floats2half2_rn(f1.x, f1.y), __floats2half2_rn(f1.z, f1.w)};
        *(uint4*)(sm + OFF_A + row * 256 + ((c ^ (row & 7)) << 4)) = *(uint4*)h;
    }
    // ---- stage all three W_j tiles -------------------------------------------
    #pragma unroll
    for (int it = 0; it < 24; ++it) {
        int p  = it * 256 + tid;           // 6144 chunks over 3 j-blocks
        int jj = p >> 11;
        int q  = p & 2047;
        int k  = q >> 4;
        int cn = q & 15;
        const float* src = W + ((size_t)jj * 128 + k) * 128 + cn * 8;
        float4 f0 = *(const float4*)src;
        float4 f1 = *(const float4*)(src + 4);
        __half2 h[4] = {__floats2half2_rn(f0.x, f0.y), __floats2half2_rn(f0.z, f0.w),
                        __floats2half2_rn(f1.x, f1.y), __floats2half2_rn(f1.z, f1.w)};
        *(uint4*)(sm + OFF_B + jj * 32768 + k * 256 + ((cn ^ (k & 7)) << 4)) =
            *(uint4*)h;
    }
    __syncthreads();

    const int arow = wid * 16 + (lane & 15);
    const uint32_t a_base = smb + OFF_A + arow * 256;
    const int a_hi = lane >> 4;
    const int a_r7 = arow & 7;
    const uint32_t b_base0 = smb + OFF_B + (lane & 15) * 256;
    const int b_hi = lane >> 4;
    const int b_r7 = lane & 7;

    const int r  = lane >> 2;
    const int q2 = (lane & 3) * 2;
    const int mA = m0 + wid * 16 + r;
    const int mB = mA + 8;
    const int bA = mA / T, tA = mA - bA * T;
    const int bB = mB / T, tB = mB - bB * T;

    #pragma unroll
    for (int j = 0; j < 3; ++j) {
        const uint32_t b_base = b_base0 + j * 32768;

        float c[16][4];
        #pragma unroll
        for (int nb = 0; nb < 16; ++nb)
            #pragma unroll
            for (int q = 0; q < 4; ++q) c[nb][q] = 0.f;

        #pragma unroll
        for (int kb = 0; kb < 8; ++kb) {
            uint32_t a0, a1, a2, a3;
            uint32_t a_addr = a_base + (((2 * kb + a_hi) ^ a_r7) << 4);
            asm volatile("ldmatrix.sync.aligned.m8n8.x4.shared.b16 {%0,%1,%2,%3}, [%4];"
                         : "=r"(a0), "=r"(a1), "=r"(a2), "=r"(a3) : "r"(a_addr));
            #pragma unroll
            for (int nb2 = 0; nb2 < 8; ++nb2) {
                uint32_t b0, b1, b2, b3;
                uint32_t b_addr = b_base + kb * 4096
                                + (((2 * nb2 + b_hi) ^ b_r7) << 4);
                asm volatile("ldmatrix.sync.aligned.m8n8.x4.trans.shared.b16 "
                             "{%0,%1,%2,%3}, [%4];"
                             : "=r"(b0), "=r"(b1), "=r"(b2), "=r"(b3) : "r"(b_addr));
                asm volatile(
                    "mma.sync.aligned.m16n8k16.row.col.f32.f16.f16.f32 "
                    "{%0,%1,%2,%3}, {%4,%5,%6,%7}, {%8,%9}, {%0,%1,%2,%3};"
                    : "+f"(c[2*nb2][0]), "+f"(c[2*nb2][1]),
                      "+f"(c[2*nb2][2]), "+f"(c[2*nb2][3])
                    : "r"(a0), "r"(a1), "r"(a2), "r"(a3), "r"(b0), "r"(b1));
                asm volatile(
                    "mma.sync.aligned.m16n8k16.row.col.f32.f16.f16.f32 "
                    "{%0,%1,%2,%3}, {%4,%5,%6,%7}, {%8,%9}, {%0,%1,%2,%3};"
                    : "+f"(c[2*nb2+1][0]), "+f"(c[2*nb2+1][1]),
                      "+f"(c[2*nb2+1][2]), "+f"(c[2*nb2+1][3])
                    : "r"(a0), "r"(a1), "r"(a2), "r"(a3), "r"(b2), "r"(b3));
            }
        }

        __half* dstA = g_Zh + (((size_t)j * T + tA) * B + bA) * 128 + q2;
        __half* dstB = g_Zh + (((size_t)j * T + tB) * B + bB) * 128 + q2;
        #pragma unroll
        for (int nb = 0; nb < 16; ++nb) {
            *(__half2*)(dstA + nb * 8) = __floats2half2_rn(c[nb][0], c[nb][1]);
            *(__half2*)(dstB + nb * 8) = __floats2half2_rn(c[nb][2], c[nb][3]);
        }
    }

    // PDL: allow the gather grid to become resident (no-op without PDL edge).
    asm volatile("griddepcontrol.launch_dependents;");
}

// --- out[b,n,:] = bias + sum_j Z[j, idx[n,j], b, :] --------------------------
// 4 vertices per block, 256 threads; per item, pairs processed with 6 Z-loads
// in flight (R6 inner shape). Preamble runs under PDL before GEMM completes.
__global__ void gather_out(const int* __restrict__ idxw,
                           const float* __restrict__ bias,
                           float* __restrict__ out, int N, int T, int B) {
    __shared__ int sh_t[12];
    const int n0 = blockIdx.x * 4;

    if (threadIdx.x < 32) {
        // int64 little-endian => every odd word is the sign extension of the
        // preceding word; int32 data with values in [-1,T) fails w.p. ~1.
        int lo = idxw[2 * threadIdx.x];
        int hi = idxw[2 * threadIdx.x + 1];
        unsigned ok = __ballot_sync(0xffffffffu, hi == ((lo < 0) ? -1 : 0));
        int s = 1 + (ok == 0xffffffffu);
        if (threadIdx.x < 12) sh_t[threadIdx.x] = idxw[(n0 * 3 + threadIdx.x) * s];
    }
    __syncthreads();

    int tt[12];
    #pragma unroll
    for (int i = 0; i < 12; ++i) tt[i] = sh_t[i];

    const uint4*  Z16 = (const uint4*)g_Zh;
    const float4* b4  = (const float4*)bias;
    const uint4   zz  = make_uint4(0u, 0u, 0u, 0u);

    // Wait for Z (no-op if PDL edge absent).
    asm volatile("griddepcontrol.wait;" ::: "memory");

    const int total = B * 16;                 // 512 items
    for (int p = threadIdx.x; p < total; p += blockDim.x) {
        const int b  = p >> 4;
        const int v8 = p & 15;
        const size_t rowoff = (size_t)b * 16 + v8;

        const float4 bsA = __ldg(b4 + v8 * 2);
        const float4 bsB = __ldg(b4 + v8 * 2 + 1);

        #pragma unroll
        for (int pr = 0; pr < 2; ++pr) {       // vertex pair (n0+2pr, n0+2pr+1)
            uint4 z[6];
            #pragma unroll
            for (int i = 0; i < 6; ++i) {
                int j = i % 3;
                int t = tt[6 * pr + i];
                z[i] = (t >= 0)
                     ? __ldcg(Z16 + ((size_t)j * T + t) * (B * 16) + rowoff)
                     : zz;
            }

            #pragma unroll
            for (int nn = 0; nn < 2; ++nn) {
                float4 accA = bsA, accB = bsB;
                #pragma unroll
                for (int j = 0; j < 3; ++j) {
                    uint4 zv = z[nn * 3 + j];
                    float2 f0 = __half22float2(*(__half2*)&zv.x);
                    float2 f1 = __half22float2(*(__half2*)&zv.y);
                    float2 f2 = __half22float2(*(__half2*)&zv.z);
                    float2 f3 = __half22float2(*(__half2*)&zv.w);
                    accA.x += f0.x; accA.y += f0.y; accA.z += f1.x; accA.w += f1.y;
                    accB.x += f2.x; accB.y += f2.y; accB.z += f3.x; accB.w += f3.y;
                }
                float* o = out + ((size_t)b * N + (n0 + 2 * pr + nn)) * 128 + v8 * 8;
                __stcs((float4*)o, accA);
                __stcs((float4*)(o + 4), accB);
            }
        }
    }
}

extern "C" void kernel_launch(void* const* d_in, const int* in_sizes, int n_in,
                              void* d_out, int out_size) {
    const float* hex  = (const float*)d_in[0];   // (B, T, D) f32
    const int*   idxw = (const int*)d_in[1];     // (N, 3) int32 or int64
    const float* W    = (const float*)d_in[2];   // (3D, V) f32
    const float* bias = (const float*)d_in[3];   // (V,) f32
    float*       out  = (float*)d_out;           // (B, N, V) f32

    const int V      = in_sizes[3];              // 128
    const int threeD = in_sizes[2] / V;          // 384
    const int D      = threeD / 3;               // 128
    const int BT     = in_sizes[0] / D;          // B*T = 16384
    const int N      = in_sizes[1] / 3;          // 20000
    const int B      = out_size / (N * V);       // 32
    const int T      = BT / B;                   // 512

    cudaFuncSetAttribute(gemm_z, cudaFuncAttributeMaxDynamicSharedMemorySize,
                         GEMM_SMEM);

    gemm_z<<<BT / 128, 256, GEMM_SMEM>>>(hex, W, T, B);

    // Gather with programmatic dependent launch: becomes resident while the
    // GEMM drains; griddepcontrol.wait gates the Z reads.
    cudaLaunchConfig_t cfg = {};
    cfg.gridDim  = dim3(N / 4, 1, 1);
    cfg.blockDim = dim3(256, 1, 1);
    cudaLaunchAttribute attr[1];
    attr[0].id = cudaLaunchAttributeProgrammaticStreamSerialization;
    attr[0].val.programmaticStreamSerializationAllowed = 1;
    cfg.attrs = attr;
    cfg.numAttrs = 1;
    cudaLaunchKernelEx(&cfg, gather_out, idxw, bias, out, N, T, B);
}

// round 15
// speedup vs baseline: 1.0384x; 1.0384x over previous
#include <cuda_runtime.h>
#include <cuda_fp16.h>
#include <cstdint>

// ---------------------------------------------------------------------------
// InflateHexToVertex, factored:
//   Z[j,t,b,v] = hex[b,t,:] @ W[j*D:(j+1)*D, :]   (mma.sync fp16 GEMM, f32 acc)
//   out[b,n,v] = bias[v] + sum_j (idx[n,j] >= 0) * Z[j, idx[n,j], b, v]
//
// Z fp16 (12.6 MB), L2-resident. Measured-best components: R11 GEMM (stage
// A + all 3 W_j once) + R6 gather (256 thr, 2 vertices, 6 loads in flight).
// PDL overlaps the gather preamble with the GEMM drain.
// ---------------------------------------------------------------------------

__device__ __half g_Zh[3 * 512 * 32 * 128];

#define OFF_A 0
#define OFF_B 32768                     // B_j at OFF_B + j*32768
#define GEMM_SMEM 131072

__device__ __forceinline__ uint32_t smem_u32(const void* p) {
    uint32_t a;
    asm("{ .reg .u64 t; cvta.to.shared.u64 t, %1; cvt.u32.u64 %0, t; }"
        : "=r"(a) : "l"(p));
    return a;
}

// --- Z = hex(16384x128) @ W(384x128) via mma.sync (R11 config) ----------------
__global__ void __launch_bounds__(256, 1)
gemm_z(const float* __restrict__ A, const float* __restrict__ W,
       int T, int B) {
    extern __shared__ char sm[];
    const uint32_t smb = smem_u32(sm);
    const int tid = threadIdx.x;
    const int wid = tid >> 5;
    const int lane = tid & 31;
    const int m0 = blockIdx.x * 128;

    // ---- stage A tile: fp32 -> fp16, swizzled --------------------------------
    #pragma unroll
    for (int it = 0; it < 8; ++it) {
        int p   = it * 256 + tid;          // 2048 chunks
        int row = p >> 4;
        int c   = p & 15;
        const float* src = A + (size_t)(m0 + row) * 128 + c * 8;
        float4 f0 = *(const float4*)src;
        float4 f1 = *(const float4*)(src + 4);
        __half2 h[4] = {__floats2half2_rn(f0.x, f0.y), __floats2half2_rn(f0.z, f0.w),
                        __floats2half2_rn(f1.x, f1.y), __floats2half2_rn(f1.z, f1.w)};
        *(uint4*)(sm + OFF_A + row * 256 + ((c ^ (row & 7)) << 4)) = *(uint4*)h;
    }
    // ---- stage all three W_j tiles -------------------------------------------
    #pragma unroll
    for (int it = 0; it < 24; ++it) {
        int p  = it * 256 + tid;           // 6144 chunks over 3 j-blocks
        int jj = p >> 11;
        int q  = p & 2047;
        int k  = q >> 4;
        int cn = q & 15;
        const float* src = W + ((size_t)jj * 128 + k) * 128 + cn * 8;
        float4 f0 = *(const float4*)src;
        float4 f1 = *(const float4*)(src + 4);
        __half2 h[4] = {__floats2half2_rn(f0.x, f0.y), __floats2half2_rn(f0.z, f0.w),
                        __floats2half2_rn(f1.x, f1.y), __floats2half2_rn(f1.z, f1.w)};
        *(uint4*)(sm + OFF_B + jj * 32768 + k * 256 + ((cn ^ (k & 7)) << 4)) =
            *(uint4*)h;
    }
    __syncthreads();

    const int arow = wid * 16 + (lane & 15);
    const uint32_t a_base = smb + OFF_A + arow * 256;
    const int a_hi = lane >> 4;
    const int a_r7 = arow & 7;
    const uint32_t b_base0 = smb + OFF_B + (lane & 15) * 256;
    const int b_hi = lane >> 4;
    const int b_r7 = lane & 7;

    const int r  = lane >> 2;
    const int q2 = (lane & 3) * 2;
    const int mA = m0 + wid * 16 + r;
    const int mB = mA + 8;
    const int bA = mA / T, tA = mA - bA * T;
    const int bB = mB / T, tB = mB - bB * T;

    #pragma unroll
    for (int j = 0; j < 3; ++j) {
        const uint32_t b_base = b_base0 + j * 32768;

        float c[16][4];
        #pragma unroll
        for (int nb = 0; nb < 16; ++nb)
            #pragma unroll
            for (int q = 0; q < 4; ++q) c[nb][q] = 0.f;

        #pragma unroll
        for (int kb = 0; kb < 8; ++kb) {
            uint32_t a0, a1, a2, a3;
            uint32_t a_addr = a_base + (((2 * kb + a_hi) ^ a_r7) << 4);
            asm volatile("ldmatrix.sync.aligned.m8n8.x4.shared.b16 {%0,%1,%2,%3}, [%4];"
                         : "=r"(a0), "=r"(a1), "=r"(a2), "=r"(a3) : "r"(a_addr));
            #pragma unroll
            for (int nb2 = 0; nb2 < 8; ++nb2) {
                uint32_t b0, b1, b2, b3;
                uint32_t b_addr = b_base + kb * 4096
                                + (((2 * nb2 + b_hi) ^ b_r7) << 4);
                asm volatile("ldmatrix.sync.aligned.m8n8.x4.trans.shared.b16 "
                             "{%0,%1,%2,%3}, [%4];"
                             : "=r"(b0), "=r"(b1), "=r"(b2), "=r"(b3) : "r"(b_addr));
                asm volatile(
                    "mma.sync.aligned.m16n8k16.row.col.f32.f16.f16.f32 "
                    "{%0,%1,%2,%3}, {%4,%5,%6,%7}, {%8,%9}, {%0,%1,%2,%3};"
                    : "+f"(c[2*nb2][0]), "+f"(c[2*nb2][1]),
                      "+f"(c[2*nb2][2]), "+f"(c[2*nb2][3])
                    : "r"(a0), "r"(a1), "r"(a2), "r"(a3), "r"(b0), "r"(b1));
                asm volatile(
                    "mma.sync.aligned.m16n8k16.row.col.f32.f16.f16.f32 "
                    "{%0,%1,%2,%3}, {%4,%5,%6,%7}, {%8,%9}, {%0,%1,%2,%3};"
                    : "+f"(c[2*nb2+1][0]), "+f"(c[2*nb2+1][1]),
                      "+f"(c[2*nb2+1][2]), "+f"(c[2*nb2+1][3])
                    : "r"(a0), "r"(a1), "r"(a2), "r"(a3), "r"(b2), "r"(b3));
            }
        }

        __half* dstA = g_Zh + (((size_t)j * T + tA) * B + bA) * 128 + q2;
        __half* dstB = g_Zh + (((size_t)j * T + tB) * B + bB) * 128 + q2;
        #pragma unroll
        for (int nb = 0; nb < 16; ++nb) {
            *(__half2*)(dstA + nb * 8) = __floats2half2_rn(c[nb][0], c[nb][1]);
            *(__half2*)(dstB + nb * 8) = __floats2half2_rn(c[nb][2], c[nb][3]);
        }
    }

    // PDL: allow the gather grid to become resident while this grid drains.
    asm volatile("griddepcontrol.launch_dependents;");
}

// --- out[b,n,:] = bias + sum_j Z[j, idx[n,j], b, :] --------------------------
// R6 shape verbatim: 2 vertices per block, 256 threads, 6 Z-loads in flight.
// Preamble (detect/idx/bias) runs under PDL before the GEMM completes.
__global__ void gather_out(const int* __restrict__ idxw,
                           const float* __restrict__ bias,
                           float* __restrict__ out, int N, int T, int B) {
    __shared__ int sh_t[6];
    const int n0 = blockIdx.x * 2;

    if (threadIdx.x < 32) {
        // int64 little-endian => every odd word is the sign extension of the
        // preceding word; int32 data with values in [-1,T) fails w.p. ~1.
        int lo = idxw[2 * threadIdx.x];
        int hi = idxw[2 * threadIdx.x + 1];
        unsigned ok = __ballot_sync(0xffffffffu, hi == ((lo < 0) ? -1 : 0));
        int s = 1 + (ok == 0xffffffffu);
        if (threadIdx.x < 6) sh_t[threadIdx.x] = idxw[(n0 * 3 + threadIdx.x) * s];
    }
    __syncthreads();

    int tt[6];
    #pragma unroll
    for (int i = 0; i < 6; ++i) tt[i] = sh_t[i];

    const uint4*  Z16 = (const uint4*)g_Zh;
    const float4* b4  = (const float4*)bias;
    const uint4   zz  = make_uint4(0u, 0u, 0u, 0u);

    // Gate the Z reads on GEMM completion (no-op if PDL edge absent).
    asm volatile("griddepcontrol.wait;" ::: "memory");

    const int total = B * 16;                 // 512 items per vertex pair
    for (int p = threadIdx.x; p < total; p += blockDim.x) {
        const int b  = p >> 4;
        const int v8 = p & 15;
        const size_t rowoff = (size_t)b * 16 + v8;

        uint4 z[6];
        #pragma unroll
        for (int i = 0; i < 6; ++i) {
            int j = i % 3;
            int t = tt[i];
            z[i] = (t >= 0)
                 ? __ldcg(Z16 + ((size_t)j * T + t) * (B * 16) + rowoff)
                 : zz;
        }

        float4 bsA = __ldg(b4 + v8 * 2);
        float4 bsB = __ldg(b4 + v8 * 2 + 1);

        #pragma unroll
        for (int nn = 0; nn < 2; ++nn) {
            float4 accA = bsA, accB = bsB;
            #pragma unroll
            for (int j = 0; j < 3; ++j) {
                uint4 zv = z[nn * 3 + j];
                float2 f0 = __half22float2(*(__half2*)&zv.x);
                float2 f1 = __half22float2(*(__half2*)&zv.y);
                float2 f2 = __half22float2(*(__half2*)&zv.z);
                float2 f3 = __half22float2(*(__half2*)&zv.w);
                accA.x += f0.x; accA.y += f0.y; accA.z += f1.x; accA.w += f1.y;
                accB.x += f2.x; accB.y += f2.y; accB.z += f3.x; accB.w += f3.y;
            }
            float* o = out + ((size_t)b * N + (n0 + nn)) * 128 + v8 * 8;
            __stcs((float4*)o, accA);
            __stcs((float4*)(o + 4), accB);
        }
    }
}

extern "C" void kernel_launch(void* const* d_in, const int* in_sizes, int n_in,
                              void* d_out, int out_size) {
    const float* hex  = (const float*)d_in[0];   // (B, T, D) f32
    const int*   idxw = (const int*)d_in[1];     // (N, 3) int32 or int64
    const float* W    = (const float*)d_in[2];   // (3D, V) f32
    const float* bias = (const float*)d_in[3];   // (V,) f32
    float*       out  = (float*)d_out;           // (B, N, V) f32

    const int V      = in_sizes[3];              // 128
    const int threeD = in_sizes[2] / V;          // 384
    const int D      = threeD / 3;               // 128
    const int BT     = in_sizes[0] / D;          // B*T = 16384
    const int N      = in_sizes[1] / 3;          // 20000
    const int B      = out_size / (N * V);       // 32
    const int T      = BT / B;                   // 512

    cudaFuncSetAttribute(gemm_z, cudaFuncAttributeMaxDynamicSharedMemorySize,
                         GEMM_SMEM);

    gemm_z<<<BT / 128, 256, GEMM_SMEM>>>(hex, W, T, B);

    // Gather with programmatic dependent launch: preamble overlaps GEMM drain.
    cudaLaunchConfig_t cfg = {};
    cfg.gridDim  = dim3(N / 2, 1, 1);
    cfg.blockDim = dim3(256, 1, 1);
    cudaLaunchAttribute attr[1];
    attr[0].id = cudaLaunchAttributeProgrammaticStreamSerialization;
    attr[0].val.programmaticStreamSerializationAllowed = 1;
    cfg.attrs = attr;
    cfg.numAttrs = 1;
    cudaLaunchKernelEx(&cfg, gather_out, idxw, bias, out, N, T, B);
}

// round 16
// speedup vs baseline: 1.0888x; 1.0486x over previous
#include <cuda_runtime.h>
#include <cuda_fp16.h>
#include <cstdint>

// ---------------------------------------------------------------------------
// InflateHexToVertex, factored:
//   Z[j,t,b,v] = hex[b,t,:] @ W[j*D:(j+1)*D, :]   (mma.sync fp16 GEMM, f32 acc)
//   out[b,n,v] = bias[v] + sum_j (idx[n,j] >= 0) * Z[j, idx[n,j], b, v]
//
// Z fp16 (12.6 MB), L2-resident. GEMM: R11 config (stage A + all 3 W_j once,
// 128 KB smem). Gather: R6 work mapping (256 thr, 2 vertices, 6 loads in
// flight) with a sync-free per-warp preamble (ballot detect + shfl broadcast
// instead of smem + 2x __syncthreads).
// ---------------------------------------------------------------------------

__device__ __half g_Zh[3 * 512 * 32 * 128];

#define OFF_A 0
#define OFF_B 32768                     // B_j at OFF_B + j*32768
#define GEMM_SMEM 131072

__device__ __forceinline__ uint32_t smem_u32(const void* p) {
    uint32_t a;
    asm("{ .reg .u64 t; cvta.to.shared.u64 t, %1; cvt.u32.u64 %0, t; }"
        : "=r"(a) : "l"(p));
    return a;
}

// --- Z = hex(16384x128) @ W(384x128) via mma.sync (R11 config) ----------------
__global__ void __launch_bounds__(256, 1)
gemm_z(const float* __restrict__ A, const float* __restrict__ W,
       int T, int B) {
    extern __shared__ char sm[];
    const uint32_t smb = smem_u32(sm);
    const int tid = threadIdx.x;
    const int wid = tid >> 5;
    const int lane = tid & 31;
    const int m0 = blockIdx.x * 128;

    // ---- stage A tile: fp32 -> fp16, swizzled --------------------------------
    #pragma unroll
    for (int it = 0; it < 8; ++it) {
        int p   = it * 256 + tid;          // 2048 chunks
        int row = p >> 4;
        int c   = p & 15;
        const float* src = A + (size_t)(m0 + row) * 128 + c * 8;
        float4 f0 = *(const float4*)src;
        float4 f1 = *(const float4*)(src + 4);
        __half2 h[4] = {__floats2half2_rn(f0.x, f0.y), __floats2half2_rn(f0.z, f0.w),
                        __floats2half2_rn(f1.x, f1.y), __floats2half2_rn(f1.z, f1.w)};
        *(uint4*)(sm + OFF_A + row * 256 + ((c ^ (row & 7)) << 4)) = *(uint4*)h;
    }
    // ---- stage all three W_j tiles -------------------------------------------
    #pragma unroll
    for (int it = 0; it < 24; ++it) {
        int p  = it * 256 + tid;           // 6144 chunks over 3 j-blocks
        int jj = p >> 11;
        int q  = p & 2047;
        int k  = q >> 4;
        int cn = q & 15;
        const float* src = W + ((size_t)jj * 128 + k) * 128 + cn * 8;
        float4 f0 = *(const float4*)src;
        float4 f1 = *(const float4*)(src + 4);
        __half2 h[4] = {__floats2half2_rn(f0.x, f0.y), __floats2half2_rn(f0.z, f0.w),
                        __floats2half2_rn(f1.x, f1.y), __floats2half2_rn(f1.z, f1.w)};
        *(uint4*)(sm + OFF_B + jj * 32768 + k * 256 + ((cn ^ (k & 7)) << 4)) =
            *(uint4*)h;
    }
    __syncthreads();

    const int arow = wid * 16 + (lane & 15);
    const uint32_t a_base = smb + OFF_A + arow * 256;
    const int a_hi = lane >> 4;
    const int a_r7 = arow & 7;
    const uint32_t b_base0 = smb + OFF_B + (lane & 15) * 256;
    const int b_hi = lane >> 4;
    const int b_r7 = lane & 7;

    const int r  = lane >> 2;
    const int q2 = (lane & 3) * 2;
    const int mA = m0 + wid * 16 + r;
    const int mB = mA + 8;
    const int bA = mA / T, tA = mA - bA * T;
    const int bB = mB / T, tB = mB - bB * T;

    #pragma unroll
    for (int j = 0; j < 3; ++j) {
        const uint32_t b_base = b_base0 + j * 32768;

        float c[16][4];
        #pragma unroll
        for (int nb = 0; nb < 16; ++nb)
            #pragma unroll
            for (int q = 0; q < 4; ++q) c[nb][q] = 0.f;

        #pragma unroll
        for (int kb = 0; kb < 8; ++kb) {
            uint32_t a0, a1, a2, a3;
            uint32_t a_addr = a_base + (((2 * kb + a_hi) ^ a_r7) << 4);
            asm volatile("ldmatrix.sync.aligned.m8n8.x4.shared.b16 {%0,%1,%2,%3}, [%4];"
                         : "=r"(a0), "=r"(a1), "=r"(a2), "=r"(a3) : "r"(a_addr));
            #pragma unroll
            for (int nb2 = 0; nb2 < 8; ++nb2) {
                uint32_t b0, b1, b2, b3;
                uint32_t b_addr = b_base + kb * 4096
                                + (((2 * nb2 + b_hi) ^ b_r7) << 4);
                asm volatile("ldmatrix.sync.aligned.m8n8.x4.trans.shared.b16 "
                             "{%0,%1,%2,%3}, [%4];"
                             : "=r"(b0), "=r"(b1), "=r"(b2), "=r"(b3) : "r"(b_addr));
                asm volatile(
                    "mma.sync.aligned.m16n8k16.row.col.f32.f16.f16.f32 "
                    "{%0,%1,%2,%3}, {%4,%5,%6,%7}, {%8,%9}, {%0,%1,%2,%3};"
                    : "+f"(c[2*nb2][0]), "+f"(c[2*nb2][1]),
                      "+f"(c[2*nb2][2]), "+f"(c[2*nb2][3])
                    : "r"(a0), "r"(a1), "r"(a2), "r"(a3), "r"(b0), "r"(b1));
                asm volatile(
                    "mma.sync.aligned.m16n8k16.row.col.f32.f16.f16.f32 "
                    "{%0,%1,%2,%3}, {%4,%5,%6,%7}, {%8,%9}, {%0,%1,%2,%3};"
                    : "+f"(c[2*nb2+1][0]), "+f"(c[2*nb2+1][1]),
                      "+f"(c[2*nb2+1][2]), "+f"(c[2*nb2+1][3])
                    : "r"(a0), "r"(a1), "r"(a2), "r"(a3), "r"(b2), "r"(b3));
            }
        }

        __half* dstA = g_Zh + (((size_t)j * T + tA) * B + bA) * 128 + q2;
        __half* dstB = g_Zh + (((size_t)j * T + tB) * B + bB) * 128 + q2;
        #pragma unroll
        for (int nb = 0; nb < 16; ++nb) {
            *(__half2*)(dstA + nb * 8) = __floats2half2_rn(c[nb][0], c[nb][1]);
            *(__half2*)(dstB + nb * 8) = __floats2half2_rn(c[nb][2], c[nb][3]);
        }
    }
}

// --- out[b,n,:] = bias + sum_j Z[j, idx[n,j], b, :] --------------------------
// R6 work mapping (2 vertices/block, 256 threads, 6 loads in flight) with a
// sync-free preamble: every warp does the dtype ballot itself (idxw head is
// L1-hot) and broadcasts the 6 indices via shfl. No smem, no __syncthreads.
__global__ void gather_out(const int* __restrict__ idxw,
                           const float* __restrict__ bias,
                           float* __restrict__ out, int N, int T, int B) {
    const int n0   = blockIdx.x * 2;
    const int lane = threadIdx.x & 31;

    // int64 little-endian => every odd word is the sign extension of the even
    // word; int32 data with values in [-1,T) fails this w.p. ~1.
    int lo = idxw[2 * lane];
    int hi = idxw[2 * lane + 1];
    unsigned ok = __ballot_sync(0xffffffffu, hi == ((lo < 0) ? -1 : 0));
    const int s = 1 + (ok == 0xffffffffu);

    int tl = (lane < 6) ? idxw[(n0 * 3 + lane) * s] : 0;
    int tt[6];
    #pragma unroll
    for (int i = 0; i < 6; ++i) tt[i] = __shfl_sync(0xffffffffu, tl, i);

    const uint4*  Z16 = (const uint4*)g_Zh;
    const float4* b4  = (const float4*)bias;
    const uint4   zz  = make_uint4(0u, 0u, 0u, 0u);

    const int total = B * 16;                 // 512 items per vertex pair
    for (int p = threadIdx.x; p < total; p += blockDim.x) {
        const int b  = p >> 4;
        const int v8 = p & 15;
        const size_t rowoff = (size_t)b * 16 + v8;

        uint4 z[6];
        #pragma unroll
        for (int i = 0; i < 6; ++i) {
            int j = i % 3;
            int t = tt[i];
            z[i] = (t >= 0)
                 ? __ldcg(Z16 + ((size_t)j * T + t) * (B * 16) + rowoff)
                 : zz;
        }

        float4 bsA = __ldg(b4 + v8 * 2);
        float4 bsB = __ldg(b4 + v8 * 2 + 1);

        #pragma unroll
        for (int nn = 0; nn < 2; ++nn) {
            float4 accA = bsA, accB = bsB;
            #pragma unroll
            for (int j = 0; j < 3; ++j) {
                uint4 zv = z[nn * 3 + j];
                float2 f0 = __half22float2(*(__half2*)&zv.x);
                float2 f1 = __half22float2(*(__half2*)&zv.y);
                float2 f2 = __half22float2(*(__half2*)&zv.z);
                float2 f3 = __half22float2(*(__half2*)&zv.w);
                accA.x += f0.x; accA.y += f0.y; accA.z += f1.x; accA.w += f1.y;
                accB.x += f2.x; accB.y += f2.y; accB.z += f3.x; accB.w += f3.y;
            }
            float* o = out + ((size_t)b * N + (n0 + nn)) * 128 + v8 * 8;
            __stcs((float4*)o, accA);
            __stcs((float4*)(o + 4), accB);
        }
    }
}

extern "C" void kernel_launch(void* const* d_in, const int* in_sizes, int n_in,
                              void* d_out, int out_size) {
    const float* hex  = (const float*)d_in[0];   // (B, T, D) f32
    const int*   idxw = (const int*)d_in[1];     // (N, 3) int32 or int64
    const float* W    = (const float*)d_in[2];   // (3D, V) f32
    const float* bias = (const float*)d_in[3];   // (V,) f32
    float*       out  = (float*)d_out;           // (B, N, V) f32

    const int V      = in_sizes[3];              // 128
    const int threeD = in_sizes[2] / V;          // 384
    const int D      = threeD / 3;               // 128
    const int BT     = in_sizes[0] / D;          // B*T = 16384
    const int N      = in_sizes[1] / 3;          // 20000
    const int B      = out_size / (N * V);       // 32
    const int T      = BT / B;                   // 512

    cudaFuncSetAttribute(gemm_z, cudaFuncAttributeMaxDynamicSharedMemorySize,
                         GEMM_SMEM);

    gemm_z<<<BT / 128, 256, GEMM_SMEM>>>(hex, W, T, B);

    gather_out<<<N / 2, 256>>>(idxw, bias, out, N, T, B);
}